// round 16
// baseline (speedup 1.0000x reference)
#include <cuda_runtime.h>
#include <cstdint>

// SpatialTransformer bilinear grid sample — bit-exact vs reference (rel_err 0.0).
// LOCKED arithmetic: fp32 serial-K FMA-chain einsum, unfused pointwise, exact
// reference association. f32x2 BANNED (R12/13). 1-thread-per-pixel BANNED (R14).
//
// R16 = R15 (shuffle-amortized coords, 4-lanes-per-pixel coalesced gathers)
//   + software-pipelined pairs of 8-pixel groups (gathers of both groups in
//     flight before interp -> MLP 8/lane, hides DRAM/L2 gather latency)
//   + st.global.cs streaming stores (write-once output, evict-first).

#define ST_B 16
#define ST_H 512
#define ST_W 512
#define ST_C 16
#define ST_HW (ST_H * ST_W)        // 262144 = 2^18
#define ST_LOG_W 9
#define ST_LOG_HW 18

// Predicated 128-bit load (R11-proven): if pred, v = *p; else keep fallback.
__device__ __forceinline__ void pld128(float4& v, const float* p, int pred) {
    asm("{\n\t"
        ".reg .pred q;\n\t"
        "setp.ne.s32 q, %5, 0;\n\t"
        "@q ld.global.nc.v4.f32 {%0,%1,%2,%3}, [%4];\n\t"
        "}"
        : "+f"(v.x), "+f"(v.y), "+f"(v.z), "+f"(v.w)
        : "l"(p), "r"(pred));
}

// Streaming 128-bit store (evict-first; output is never re-read).
__device__ __forceinline__ void stcs128(float* p, const float4& v) {
    asm volatile("st.global.cs.v4.f32 [%0], {%1,%2,%3,%4};"
                 :: "l"(p), "f"(v.x), "f"(v.y), "f"(v.z), "f"(v.w) : "memory");
}

struct Corners { float4 p00, p01, p10, p11; float wa, wb, wc, wd; uint32_t sub; };

// Gather stage for one 8-pixel group (R15-verbatim addressing/dedup).
__device__ __forceinline__ Corners st_gather(
    const float* __restrict__ img, uint32_t co, uint32_t sub, uint32_t i,
    float wa, float wb, float wc, float wd, uint32_t offp)
{
    Corners c;
    const uint32_t src = i * 8u + sub;

    c.wa = __shfl_sync(0xffffffffu, wa, src);
    c.wb = __shfl_sync(0xffffffffu, wb, src);
    c.wc = __shfl_sync(0xffffffffu, wc, src);
    c.wd = __shfl_sync(0xffffffffu, wd, src);
    const uint32_t op = __shfl_sync(0xffffffffu, offp, src);

    const int lx  = (int)(op & 1u);
    const int ly  = (int)((op >> 1) & 1u);
    const float* p00p = img + ((op & ~0xFu) + co);

    c.p00 = __ldg((const float4*)p00p);

    c.p10 = c.p00;                               // fallback: x collapsed
    pld128(c.p10, p00p + ST_C, lx);

    c.p01 = c.p00;                               // fallback: y collapsed
    pld128(c.p01, p00p + (ST_W * ST_C), ly);

    c.p11 = lx ? c.p10 : c.p01;                  // collapsed reuse
    pld128(c.p11, p00p + (ST_W * ST_C) + ST_C, lx & ly);

    c.sub = src;
    return c;
}

// LOCKED interpolation + streaming store.
__device__ __forceinline__ void st_interp(float* outw, uint32_t co, const Corners& c)
{
    float4 r;
    r.x = __fadd_rn(__fadd_rn(__fadd_rn(__fmul_rn(c.wa, c.p00.x), __fmul_rn(c.wb, c.p01.x)),
                              __fmul_rn(c.wc, c.p10.x)), __fmul_rn(c.wd, c.p11.x));
    r.y = __fadd_rn(__fadd_rn(__fadd_rn(__fmul_rn(c.wa, c.p00.y), __fmul_rn(c.wb, c.p01.y)),
                              __fmul_rn(c.wc, c.p10.y)), __fmul_rn(c.wd, c.p11.y));
    r.z = __fadd_rn(__fadd_rn(__fadd_rn(__fmul_rn(c.wa, c.p00.z), __fmul_rn(c.wb, c.p01.z)),
                              __fmul_rn(c.wc, c.p10.z)), __fmul_rn(c.wd, c.p11.z));
    r.w = __fadd_rn(__fadd_rn(__fadd_rn(__fmul_rn(c.wa, c.p00.w), __fmul_rn(c.wb, c.p01.w)),
                              __fmul_rn(c.wc, c.p10.w)), __fmul_rn(c.wd, c.p11.w));
    stcs128(outw + (c.sub * ST_C + co), r);
}

__global__ __launch_bounds__(256)
void st_bilinear_kernel(const float* __restrict__ images,
                        const float* __restrict__ theta,
                        float* __restrict__ out)
{
    const uint32_t lane      = threadIdx.x & 31u;
    const uint32_t warp_base = blockIdx.x * 256u + (threadIdx.x & ~31u);
    const uint32_t mypix     = warp_base + lane;

    const uint32_t b  = mypix >> ST_LOG_HW;           // warp-uniform
    const uint32_t yo = (mypix >> ST_LOG_W) & (ST_H - 1);
    const uint32_t xo = mypix & (ST_W - 1);

    const float* th = theta + b * 6;
    const float2 ta = __ldg((const float2*)(th + 0));
    const float2 tb = __ldg((const float2*)(th + 2));
    const float2 tc = __ldg((const float2*)(th + 4));
    const float t00 = ta.x, t01 = ta.y, t02 = tb.x;
    const float t10 = tb.y, t11 = tc.x, t12 = tc.y;

    const float xof = (float)xo;
    const float yof = (float)yo;

    // --- einsum: fp32 serial-K FMA chain (LOCKED) --------------------------
    float xn = __fadd_rn(__fmaf_rn(t01, yof, __fmul_rn(t00, xof)), t02);
    float yn = __fadd_rn(__fmaf_rn(t11, yof, __fmul_rn(t10, xof)), t12);

    // --- affine: 0.5*((x+1)*W - 1), unfused (LOCKED) -----------------------
    float x = __fmul_rn(0.5f, __fsub_rn(__fmul_rn(__fadd_rn(xn, 1.0f), (float)ST_W), 1.0f));
    float y = __fmul_rn(0.5f, __fsub_rn(__fmul_rn(__fadd_rn(yn, 1.0f), (float)ST_H), 1.0f));

    const int xf = __float2int_rd(x);
    const int yf = __float2int_rd(y);
    const int x0 = min(max(xf,     0), ST_W - 1);
    const int x1 = min(max(xf + 1, 0), ST_W - 1);
    const int y0 = min(max(yf,     0), ST_H - 1);
    const int y1 = min(max(yf + 1, 0), ST_H - 1);

    const float x0f = (float)x0, x1f = (float)x1;
    const float y0f = (float)y0, y1f = (float)y1;

    const float dx1 = __fsub_rn(x1f, x);
    const float dx0 = __fsub_rn(x, x0f);
    const float dy1 = __fsub_rn(y1f, y);
    const float dy0 = __fsub_rn(y, y0f);

    const float wa = __fmul_rn(dx1, dy1);
    const float wb = __fmul_rn(dx1, dy0);
    const float wc = __fmul_rn(dx0, dy1);
    const float wd = __fmul_rn(dx0, dy0);

    const uint32_t offp = ((((uint32_t)y0 << ST_LOG_W) + (uint32_t)x0) << 4)
                        | (uint32_t)(x1 != x0) | ((uint32_t)(y1 != y0) << 1);

    const float* img = images + (size_t)b * (ST_HW * ST_C);
    const uint32_t co  = (lane & 3u) * 4u;
    const uint32_t sub = lane >> 2;
    float* outw = out + (size_t)warp_base * ST_C;

    // --- stage 2: pipelined pairs of 8-pixel groups ------------------------
#pragma unroll
    for (uint32_t i = 0; i < 4; i += 2) {
        Corners cA = st_gather(img, co, sub, i,     wa, wb, wc, wd, offp);
        Corners cB = st_gather(img, co, sub, i + 1, wa, wb, wc, wd, offp);
        st_interp(outw, co, cA);
        st_interp(outw, co, cB);
    }
}

extern "C" void kernel_launch(void* const* d_in, const int* in_sizes, int n_in,
                              void* d_out, int out_size)
{
    const float* images = (const float*)d_in[0];
    const float* theta  = (const float*)d_in[1];
    if (n_in >= 2 && in_sizes[0] < in_sizes[1]) {   // theta is the 96-elem buffer
        images = (const float*)d_in[1];
        theta  = (const float*)d_in[0];
    }
    float* out = (float*)d_out;

    const uint32_t total  = (uint32_t)ST_B * ST_HW;   // one thread per pixel-chain
    const uint32_t blocks = total / 256u;
    st_bilinear_kernel<<<blocks, 256>>>(images, theta, out);
}

// round 17
// speedup vs baseline: 1.0532x; 1.0532x over previous
#include <cuda_runtime.h>
#include <cstdint>

// SpatialTransformer bilinear grid sample — bit-exact vs reference (rel_err 0.0).
// LOCKED arithmetic: fp32 serial-K FMA-chain einsum, unfused pointwise, exact
// reference association. f32x2 BANNED (R12/13). 1-thread-per-pixel BANNED (R14).
//
// R18 = R16 (shuffle-amortized coords + pipelined 8-pixel group pairs (MLP 8)
//            + st.global.cs streaming stores)
//     + __launch_bounds__(256, 6): cap at 42 regs so 6 CTAs/SM fit (R16's 44
//       regs cost a CTA -> occ 46%, which negated the ILP win; R15 ran 6 CTAs).

#define ST_B 16
#define ST_H 512
#define ST_W 512
#define ST_C 16
#define ST_HW (ST_H * ST_W)        // 262144 = 2^18
#define ST_LOG_W 9
#define ST_LOG_HW 18

// Predicated 128-bit load (R11-proven): if pred, v = *p; else keep fallback.
__device__ __forceinline__ void pld128(float4& v, const float* p, int pred) {
    asm("{\n\t"
        ".reg .pred q;\n\t"
        "setp.ne.s32 q, %5, 0;\n\t"
        "@q ld.global.nc.v4.f32 {%0,%1,%2,%3}, [%4];\n\t"
        "}"
        : "+f"(v.x), "+f"(v.y), "+f"(v.z), "+f"(v.w)
        : "l"(p), "r"(pred));
}

// Streaming 128-bit store (evict-first; output is never re-read).
__device__ __forceinline__ void stcs128(float* p, const float4& v) {
    asm volatile("st.global.cs.v4.f32 [%0], {%1,%2,%3,%4};"
                 :: "l"(p), "f"(v.x), "f"(v.y), "f"(v.z), "f"(v.w) : "memory");
}

struct Corners { float4 p00, p01, p10, p11; float wa, wb, wc, wd; uint32_t sub; };

// Gather stage for one 8-pixel group (R15-verbatim addressing/dedup).
__device__ __forceinline__ Corners st_gather(
    const float* __restrict__ img, uint32_t co, uint32_t sub, uint32_t i,
    float wa, float wb, float wc, float wd, uint32_t offp)
{
    Corners c;
    const uint32_t src = i * 8u + sub;

    c.wa = __shfl_sync(0xffffffffu, wa, src);
    c.wb = __shfl_sync(0xffffffffu, wb, src);
    c.wc = __shfl_sync(0xffffffffu, wc, src);
    c.wd = __shfl_sync(0xffffffffu, wd, src);
    const uint32_t op = __shfl_sync(0xffffffffu, offp, src);

    const int lx  = (int)(op & 1u);
    const int ly  = (int)((op >> 1) & 1u);
    const float* p00p = img + ((op & ~0xFu) + co);

    c.p00 = __ldg((const float4*)p00p);

    c.p10 = c.p00;                               // fallback: x collapsed
    pld128(c.p10, p00p + ST_C, lx);

    c.p01 = c.p00;                               // fallback: y collapsed
    pld128(c.p01, p00p + (ST_W * ST_C), ly);

    c.p11 = lx ? c.p10 : c.p01;                  // collapsed reuse
    pld128(c.p11, p00p + (ST_W * ST_C) + ST_C, lx & ly);

    c.sub = src;
    return c;
}

// LOCKED interpolation + streaming store.
__device__ __forceinline__ void st_interp(float* outw, uint32_t co, const Corners& c)
{
    float4 r;
    r.x = __fadd_rn(__fadd_rn(__fadd_rn(__fmul_rn(c.wa, c.p00.x), __fmul_rn(c.wb, c.p01.x)),
                              __fmul_rn(c.wc, c.p10.x)), __fmul_rn(c.wd, c.p11.x));
    r.y = __fadd_rn(__fadd_rn(__fadd_rn(__fmul_rn(c.wa, c.p00.y), __fmul_rn(c.wb, c.p01.y)),
                              __fmul_rn(c.wc, c.p10.y)), __fmul_rn(c.wd, c.p11.y));
    r.z = __fadd_rn(__fadd_rn(__fadd_rn(__fmul_rn(c.wa, c.p00.z), __fmul_rn(c.wb, c.p01.z)),
                              __fmul_rn(c.wc, c.p10.z)), __fmul_rn(c.wd, c.p11.z));
    r.w = __fadd_rn(__fadd_rn(__fadd_rn(__fmul_rn(c.wa, c.p00.w), __fmul_rn(c.wb, c.p01.w)),
                              __fmul_rn(c.wc, c.p10.w)), __fmul_rn(c.wd, c.p11.w));
    stcs128(outw + (c.sub * ST_C + co), r);
}

__global__ __launch_bounds__(256, 6)
void st_bilinear_kernel(const float* __restrict__ images,
                        const float* __restrict__ theta,
                        float* __restrict__ out)
{
    const uint32_t lane      = threadIdx.x & 31u;
    const uint32_t warp_base = blockIdx.x * 256u + (threadIdx.x & ~31u);
    const uint32_t mypix     = warp_base + lane;

    const uint32_t b  = mypix >> ST_LOG_HW;           // warp-uniform
    const uint32_t yo = (mypix >> ST_LOG_W) & (ST_H - 1);
    const uint32_t xo = mypix & (ST_W - 1);

    const float* th = theta + b * 6;
    const float2 ta = __ldg((const float2*)(th + 0));
    const float2 tb = __ldg((const float2*)(th + 2));
    const float2 tc = __ldg((const float2*)(th + 4));
    const float t00 = ta.x, t01 = ta.y, t02 = tb.x;
    const float t10 = tb.y, t11 = tc.x, t12 = tc.y;

    const float xof = (float)xo;
    const float yof = (float)yo;

    // --- einsum: fp32 serial-K FMA chain (LOCKED) --------------------------
    float xn = __fadd_rn(__fmaf_rn(t01, yof, __fmul_rn(t00, xof)), t02);
    float yn = __fadd_rn(__fmaf_rn(t11, yof, __fmul_rn(t10, xof)), t12);

    // --- affine: 0.5*((x+1)*W - 1), unfused (LOCKED) -----------------------
    float x = __fmul_rn(0.5f, __fsub_rn(__fmul_rn(__fadd_rn(xn, 1.0f), (float)ST_W), 1.0f));
    float y = __fmul_rn(0.5f, __fsub_rn(__fmul_rn(__fadd_rn(yn, 1.0f), (float)ST_H), 1.0f));

    const int xf = __float2int_rd(x);
    const int yf = __float2int_rd(y);
    const int x0 = min(max(xf,     0), ST_W - 1);
    const int x1 = min(max(xf + 1, 0), ST_W - 1);
    const int y0 = min(max(yf,     0), ST_H - 1);
    const int y1 = min(max(yf + 1, 0), ST_H - 1);

    const float x0f = (float)x0, x1f = (float)x1;
    const float y0f = (float)y0, y1f = (float)y1;

    const float dx1 = __fsub_rn(x1f, x);
    const float dx0 = __fsub_rn(x, x0f);
    const float dy1 = __fsub_rn(y1f, y);
    const float dy0 = __fsub_rn(y, y0f);

    const float wa = __fmul_rn(dx1, dy1);
    const float wb = __fmul_rn(dx1, dy0);
    const float wc = __fmul_rn(dx0, dy1);
    const float wd = __fmul_rn(dx0, dy0);

    const uint32_t offp = ((((uint32_t)y0 << ST_LOG_W) + (uint32_t)x0) << 4)
                        | (uint32_t)(x1 != x0) | ((uint32_t)(y1 != y0) << 1);

    const float* img = images + (size_t)b * (ST_HW * ST_C);
    const uint32_t co  = (lane & 3u) * 4u;
    const uint32_t sub = lane >> 2;
    float* outw = out + (size_t)warp_base * ST_C;

    // --- stage 2: pipelined pairs of 8-pixel groups ------------------------
#pragma unroll
    for (uint32_t i = 0; i < 4; i += 2) {
        Corners cA = st_gather(img, co, sub, i,     wa, wb, wc, wd, offp);
        Corners cB = st_gather(img, co, sub, i + 1, wa, wb, wc, wd, offp);
        st_interp(outw, co, cA);
        st_interp(outw, co, cB);
    }
}

extern "C" void kernel_launch(void* const* d_in, const int* in_sizes, int n_in,
                              void* d_out, int out_size)
{
    const float* images = (const float*)d_in[0];
    const float* theta  = (const float*)d_in[1];
    if (n_in >= 2 && in_sizes[0] < in_sizes[1]) {   // theta is the 96-elem buffer
        images = (const float*)d_in[1];
        theta  = (const float*)d_in[0];
    }
    float* out = (float*)d_out;

    const uint32_t total  = (uint32_t)ST_B * ST_HW;   // one thread per pixel-chain
    const uint32_t blocks = total / 256u;
    st_bilinear_kernel<<<blocks, 256>>>(images, theta, out);
}